// round 8
// baseline (speedup 1.0000x reference)
#include <cuda_runtime.h>
#include <cuda_bf16.h>
#include <cstdint>

#define Nn   50000
#define Ee   800000
#define Rr   10
#define Bb   4
#define Dd   64   // D_IN == D_OUT == 64

// Scratch (no allocation allowed -> __device__ globals).
__device__ __align__(16) float W_dev[(Rr + 1) * Dd * Dd];   // tf32 bit patterns
__device__ __align__(16) float xr_buf[(size_t)Rr * Nn * Dd]; // 128 MB
__device__ int   counts_dev[Nn];
__device__ int   offsets_dev[Nn + 1];
__device__ int   cursor_dev[Nn];
__device__ __align__(8) uint2 sorted_dev[Ee];   // {xr row offset, norm bits}

__device__ __forceinline__ uint32_t f32_to_tf32(float f) {
    uint32_t t;
    asm("cvt.rna.tf32.f32 %0, %1;" : "=r"(t) : "f"(f));
    return t;
}

// ---------------------------------------------------------------------------
// K0: zero the dst histogram
// ---------------------------------------------------------------------------
__global__ void k_zero() {
    int i = blockIdx.x * blockDim.x + threadIdx.x;
    if (i < Nn) counts_dev[i] = 0;
}

// ---------------------------------------------------------------------------
// K1: basis combine  W[r] = sum_b w_comp[r,b] * weight[b];  W[R] = self_loop
// ---------------------------------------------------------------------------
__global__ void k_basis(const float* __restrict__ weight,
                        const float* __restrict__ w_comp,
                        const float* __restrict__ selfw) {
    int idx = blockIdx.x * blockDim.x + threadIdx.x;   // over (R+1)*4096
    if (idx < Rr * Dd * Dd) {
        int r  = idx >> 12;
        int io = idx & 4095;
        float s = 0.f;
#pragma unroll
        for (int b = 0; b < Bb; b++)
            s += w_comp[r * Bb + b] * weight[b * Dd * Dd + io];
        ((uint32_t*)W_dev)[idx] = f32_to_tf32(s);
    } else if (idx < (Rr + 1) * Dd * Dd) {
        ((uint32_t*)W_dev)[idx] = f32_to_tf32(selfw[idx - Rr * Dd * Dd]);
    }
}

// ---------------------------------------------------------------------------
// K2: histogram of dst
// ---------------------------------------------------------------------------
__global__ __launch_bounds__(256) void k_hist(const int* __restrict__ dst) {
    int e = blockIdx.x * blockDim.x + threadIdx.x;
    if (e < Ee) atomicAdd(&counts_dev[__ldg(dst + e)], 1);
}

// ---------------------------------------------------------------------------
// K3: single-block exclusive scan of counts -> offsets (+ cursor copy)
// ---------------------------------------------------------------------------
#define SCAN_T 1024
#define CHUNK  49   // 1024*49 = 50176 >= 50000
__global__ __launch_bounds__(SCAN_T) void k_scan() {
    __shared__ int s[SCAN_T];
    const int t = threadIdx.x;
    const int base = t * CHUNK;

    int sum = 0;
#pragma unroll 7
    for (int i = 0; i < CHUNK; i++) {
        int idx = base + i;
        if (idx < Nn) sum += counts_dev[idx];
    }
    s[t] = sum;
    __syncthreads();
    // Hillis-Steele inclusive scan over 1024 partials
    for (int ofs = 1; ofs < SCAN_T; ofs <<= 1) {
        int v = (t >= ofs) ? s[t - ofs] : 0;
        __syncthreads();
        s[t] += v;
        __syncthreads();
    }
    int run = (t == 0) ? 0 : s[t - 1];
    for (int i = 0; i < CHUNK; i++) {
        int idx = base + i;
        if (idx < Nn) {
            offsets_dev[idx] = run;
            cursor_dev[idx]  = run;
            run += counts_dev[idx];
        }
    }
    if (t == 0) offsets_dev[Nn] = Ee;
}

// ---------------------------------------------------------------------------
// K4: reorder edges by dst; record = {xr row offset, norm bits}
// ---------------------------------------------------------------------------
__global__ __launch_bounds__(256) void k_reorder(const int* __restrict__ src,
                                                 const int* __restrict__ dst,
                                                 const int* __restrict__ etype,
                                                 const float* __restrict__ norm) {
    int e = blockIdx.x * blockDim.x + threadIdx.x;
    if (e >= Ee) return;
    int d   = __ldg(dst + e);
    int pos = atomicAdd(&cursor_dev[d], 1);
    uint32_t ofs = (uint32_t)((__ldg(etype + e) * Nn + __ldg(src + e)) * Dd);
    sorted_dev[pos] = make_uint2(ofs, __float_as_uint(__ldg(norm + e)));
}

// ---------------------------------------------------------------------------
// K5: per-relation GEMM on tensor cores (mma.sync m16n8k8 tf32).
// CTA: 128 M x 64 N, K=64. 4 warps, warp tile 32M x 64N.
// blockIdx.y = relation r (r==R -> self-loop straight into d_out, pre-ReLU).
// ---------------------------------------------------------------------------
#define SLD 68
#define GEMM_SMEM ((128 * SLD + 64 * SLD) * 4)   // 52224 bytes

__global__ __launch_bounds__(128) void k_gemm(const float* __restrict__ feat,
                                              float* __restrict__ d_out) {
    extern __shared__ uint32_t sh[];
    uint32_t* As = sh;                 // [128][SLD]
    uint32_t* Bs = sh + 128 * SLD;     // [64][SLD], stored [n][k]

    const int r   = blockIdx.y;
    const int nb  = blockIdx.x * 128;
    const int tid = threadIdx.x;

    {
        const uint32_t* Wsrc = (const uint32_t*)W_dev + r * Dd * Dd;  // [k][n]
#pragma unroll
        for (int it = 0; it < 32; it++) {
            int idx = tid + it * 128;
            int k = idx >> 6, n = idx & 63;
            Bs[n * SLD + k] = Wsrc[idx];
        }
    }
#pragma unroll
    for (int it = 0; it < 16; it++) {
        int lin = tid + it * 128;
        int m   = lin >> 4;
        int k4  = (lin & 15) << 2;
        int node = nb + m;
        float4 v = make_float4(0.f, 0.f, 0.f, 0.f);
        if (node < Nn) v = *(const float4*)(feat + (size_t)node * Dd + k4);
        uint32_t* p = As + m * SLD + k4;
        p[0] = f32_to_tf32(v.x); p[1] = f32_to_tf32(v.y);
        p[2] = f32_to_tf32(v.z); p[3] = f32_to_tf32(v.w);
    }
    __syncthreads();

    const int lane = tid & 31;
    const int warp = tid >> 5;
    const int g    = lane >> 2;
    const int tig  = lane & 3;
    const int mb   = warp * 32;

    float acc[2][8][4];
#pragma unroll
    for (int mf = 0; mf < 2; mf++)
#pragma unroll
        for (int nf = 0; nf < 8; nf++)
#pragma unroll
            for (int j = 0; j < 4; j++) acc[mf][nf][j] = 0.f;

#pragma unroll
    for (int k0 = 0; k0 < 64; k0 += 8) {
        uint32_t a[2][4];
#pragma unroll
        for (int mf = 0; mf < 2; mf++) {
            int row = mb + mf * 16 + g;
            a[mf][0] = As[row * SLD + k0 + tig];
            a[mf][1] = As[(row + 8) * SLD + k0 + tig];
            a[mf][2] = As[row * SLD + k0 + tig + 4];
            a[mf][3] = As[(row + 8) * SLD + k0 + tig + 4];
        }
#pragma unroll
        for (int nf = 0; nf < 8; nf++) {
            uint32_t b0 = Bs[(nf * 8 + g) * SLD + k0 + tig];
            uint32_t b1 = Bs[(nf * 8 + g) * SLD + k0 + tig + 4];
#pragma unroll
            for (int mf = 0; mf < 2; mf++) {
                asm volatile(
                    "mma.sync.aligned.m16n8k8.row.col.f32.tf32.tf32.f32 "
                    "{%0,%1,%2,%3}, {%4,%5,%6,%7}, {%8,%9}, {%0,%1,%2,%3};"
                    : "+f"(acc[mf][nf][0]), "+f"(acc[mf][nf][1]),
                      "+f"(acc[mf][nf][2]), "+f"(acc[mf][nf][3])
                    : "r"(a[mf][0]), "r"(a[mf][1]), "r"(a[mf][2]), "r"(a[mf][3]),
                      "r"(b0), "r"(b1));
            }
        }
    }

    float* outbase = (r < Rr) ? (xr_buf + (size_t)r * Nn * Dd) : d_out;
#pragma unroll
    for (int mf = 0; mf < 2; mf++) {
#pragma unroll
        for (int h = 0; h < 2; h++) {
            int row = nb + mb + mf * 16 + g + h * 8;
            if (row < Nn) {
                float* rp = outbase + (size_t)row * Dd + 2 * tig;
#pragma unroll
                for (int nf = 0; nf < 8; nf++) {
                    float2 v = make_float2(acc[mf][nf][2 * h], acc[mf][nf][2 * h + 1]);
                    *(float2*)(rp + nf * 8) = v;
                }
            }
        }
    }
}

// ---------------------------------------------------------------------------
// K6: atomic-free segmented aggregation + self-loop + ReLU (fused epilogue).
// 16 threads per dst node (4 cols each) walk the node's sorted edge segment.
// ---------------------------------------------------------------------------
__global__ __launch_bounds__(256) void k_agg(float* __restrict__ out) {
    const int tid  = threadIdx.x;
    const int node = blockIdx.x * 16 + (tid >> 4);
    const int c4   = (tid & 15) << 2;
    if (node >= Nn) return;

    int j   = offsets_dev[node];
    int end = offsets_dev[node + 1];

    float4 acc = make_float4(0.f, 0.f, 0.f, 0.f);
    // 2-deep unrolled for MLP
    for (; j + 1 < end; j += 2) {
        uint2 r0 = sorted_dev[j];
        uint2 r1 = sorted_dev[j + 1];
        float4 v0 = *(const float4*)(xr_buf + r0.x + c4);
        float4 v1 = *(const float4*)(xr_buf + r1.x + c4);
        float  n0 = __uint_as_float(r0.y);
        float  n1 = __uint_as_float(r1.y);
        acc.x = fmaf(n0, v0.x, acc.x); acc.y = fmaf(n0, v0.y, acc.y);
        acc.z = fmaf(n0, v0.z, acc.z); acc.w = fmaf(n0, v0.w, acc.w);
        acc.x = fmaf(n1, v1.x, acc.x); acc.y = fmaf(n1, v1.y, acc.y);
        acc.z = fmaf(n1, v1.z, acc.z); acc.w = fmaf(n1, v1.w, acc.w);
    }
    if (j < end) {
        uint2 r0 = sorted_dev[j];
        float4 v0 = *(const float4*)(xr_buf + r0.x + c4);
        float  n0 = __uint_as_float(r0.y);
        acc.x = fmaf(n0, v0.x, acc.x); acc.y = fmaf(n0, v0.y, acc.y);
        acc.z = fmaf(n0, v0.z, acc.z); acc.w = fmaf(n0, v0.w, acc.w);
    }

    float* rp = out + (size_t)node * Dd + c4;
    float4 self = *(const float4*)rp;   // self-loop GEMM result (pre-ReLU)
    float4 h;
    h.x = fmaxf(self.x + acc.x, 0.f);
    h.y = fmaxf(self.y + acc.y, 0.f);
    h.z = fmaxf(self.z + acc.z, 0.f);
    h.w = fmaxf(self.w + acc.w, 0.f);
    *(float4*)rp = h;
}

// ---------------------------------------------------------------------------
// Inputs (metadata order): feat, src, dst, etype, norm, weight, w_comp,
//                          self_loop_weight.  Output: float [N, 64].
// ---------------------------------------------------------------------------
extern "C" void kernel_launch(void* const* d_in, const int* in_sizes, int n_in,
                              void* d_out, int out_size) {
    const float* feat   = (const float*)d_in[0];
    const int*   src    = (const int*)d_in[1];
    const int*   dst    = (const int*)d_in[2];
    const int*   etype  = (const int*)d_in[3];
    const float* norm   = (const float*)d_in[4];
    const float* weight = (const float*)d_in[5];
    const float* w_comp = (const float*)d_in[6];
    const float* selfw  = (const float*)d_in[7];
    float* out = (float*)d_out;

    cudaFuncSetAttribute(k_gemm, cudaFuncAttributeMaxDynamicSharedMemorySize,
                         GEMM_SMEM);

    // Sort machinery (independent of W; runs while nothing else is pending)
    k_zero<<<(Nn + 255) / 256, 256>>>();
    k_basis<<<176, 256>>>(weight, w_comp, selfw);
    k_hist<<<(Ee + 255) / 256, 256>>>(dst);
    k_scan<<<1, SCAN_T>>>();
    k_reorder<<<(Ee + 255) / 256, 256>>>(src, dst, etype, norm);

    // 11 relation GEMMs (slot R -> d_out pre-ReLU, fully overwrites out)
    dim3 g2((Nn + 127) / 128, Rr + 1);
    k_gemm<<<g2, 128, GEMM_SMEM>>>(feat, out);

    // Atomic-free aggregation + self-loop + ReLU
    k_agg<<<(Nn + 15) / 16, 256>>>(out);
}

// round 10
// speedup vs baseline: 1.8579x; 1.8579x over previous
#include <cuda_runtime.h>
#include <cuda_bf16.h>
#include <cuda_fp16.h>
#include <cstdint>

#define Nn   50000
#define Ee   800000
#define Rr   10
#define Bb   4
#define Dd   64   // D_IN == D_OUT == 64
#define NB   ((Nn + 255) / 256)   // 196 scan blocks

// Scratch (no allocation allowed -> __device__ globals).
__device__ __align__(16) float  W_dev[(Rr + 1) * Dd * Dd];      // tf32 bits
__device__ __align__(16) __half xr_h[(size_t)Rr * Nn * Dd];     // 64 MB, L2-resident
__device__ int   counts_dev[Nn];
__device__ int   offsets_dev[Nn + 1];
__device__ int   cursor_dev[Nn];
__device__ int   blocksum_dev[NB];
__device__ int   blockofs_dev[NB];
__device__ __align__(8) uint2 sorted_dev[Ee];   // {xr element offset, norm bits}

__device__ __forceinline__ uint32_t f32_to_tf32(float f) {
    uint32_t t;
    asm("cvt.rna.tf32.f32 %0, %1;" : "=r"(t) : "f"(f));
    return t;
}

// ---------------------------------------------------------------------------
// K0: zero the dst histogram
// ---------------------------------------------------------------------------
__global__ void k_zero() {
    int i = blockIdx.x * blockDim.x + threadIdx.x;
    if (i < Nn) counts_dev[i] = 0;
}

// ---------------------------------------------------------------------------
// K1: basis combine  W[r] = sum_b w_comp[r,b] * weight[b];  W[R] = self_loop
// ---------------------------------------------------------------------------
__global__ void k_basis(const float* __restrict__ weight,
                        const float* __restrict__ w_comp,
                        const float* __restrict__ selfw) {
    int idx = blockIdx.x * blockDim.x + threadIdx.x;   // over (R+1)*4096
    if (idx < Rr * Dd * Dd) {
        int r  = idx >> 12;
        int io = idx & 4095;
        float s = 0.f;
#pragma unroll
        for (int b = 0; b < Bb; b++)
            s += w_comp[r * Bb + b] * weight[b * Dd * Dd + io];
        ((uint32_t*)W_dev)[idx] = f32_to_tf32(s);
    } else if (idx < (Rr + 1) * Dd * Dd) {
        ((uint32_t*)W_dev)[idx] = f32_to_tf32(selfw[idx - Rr * Dd * Dd]);
    }
}

// ---------------------------------------------------------------------------
// K2: histogram of dst
// ---------------------------------------------------------------------------
__global__ __launch_bounds__(256) void k_hist(const int* __restrict__ dst) {
    int e = blockIdx.x * blockDim.x + threadIdx.x;
    if (e < Ee) atomicAdd(&counts_dev[__ldg(dst + e)], 1);
}

// ---------------------------------------------------------------------------
// K3a/b/c: parallel exclusive scan of counts -> offsets (+ cursor copy).
// 196 blocks x 256 threads; tiny top-level scan in one block.
// ---------------------------------------------------------------------------
__global__ __launch_bounds__(256) void k_scan_block() {
    __shared__ int ws[8];
    int i = blockIdx.x * 256 + threadIdx.x;
    int v = (i < Nn) ? counts_dev[i] : 0;
    int lane = threadIdx.x & 31, w = threadIdx.x >> 5;
    int s = v;
#pragma unroll
    for (int o = 16; o; o >>= 1) s += __shfl_down_sync(~0u, s, o);
    if (lane == 0) ws[w] = s;
    __syncthreads();
    if (w == 0) {
        int t = (lane < 8) ? ws[lane] : 0;
#pragma unroll
        for (int o = 4; o; o >>= 1) t += __shfl_down_sync(~0u, t, o);
        if (lane == 0) blocksum_dev[blockIdx.x] = t;
    }
}

__global__ __launch_bounds__(256) void k_scan_top() {
    __shared__ int ws[8];
    int t = threadIdx.x;
    int v = (t < NB) ? blocksum_dev[t] : 0;
    int lane = t & 31, w = t >> 5;
    int incl = v;
#pragma unroll
    for (int o = 1; o < 32; o <<= 1) {
        int x = __shfl_up_sync(~0u, incl, o);
        if (lane >= o) incl += x;
    }
    if (lane == 31) ws[w] = incl;
    __syncthreads();
    if (w == 0 && lane < 8) {
        int x = ws[lane], inc = x;
#pragma unroll
        for (int o = 1; o < 8; o <<= 1) {
            int y = __shfl_up_sync(0xff, inc, o);
            if (lane >= o) inc += y;
        }
        ws[lane] = inc - x;   // exclusive warp bases
    }
    __syncthreads();
    if (t < NB) blockofs_dev[t] = ws[w] + incl - v;   // exclusive
}

__global__ __launch_bounds__(256) void k_scan_down() {
    __shared__ int ws[8];
    int i = blockIdx.x * 256 + threadIdx.x;
    int v = (i < Nn) ? counts_dev[i] : 0;
    int lane = threadIdx.x & 31, w = threadIdx.x >> 5;
    int incl = v;
#pragma unroll
    for (int o = 1; o < 32; o <<= 1) {
        int x = __shfl_up_sync(~0u, incl, o);
        if (lane >= o) incl += x;
    }
    if (lane == 31) ws[w] = incl;
    __syncthreads();
    if (w == 0 && lane < 8) {
        int x = ws[lane], inc = x;
#pragma unroll
        for (int o = 1; o < 8; o <<= 1) {
            int y = __shfl_up_sync(0xff, inc, o);
            if (lane >= o) inc += y;
        }
        ws[lane] = inc - x;
    }
    __syncthreads();
    if (i < Nn) {
        int excl = blockofs_dev[blockIdx.x] + ws[w] + incl - v;
        offsets_dev[i] = excl;
        cursor_dev[i]  = excl;
    }
    if (i == 0) offsets_dev[Nn] = Ee;
}

// ---------------------------------------------------------------------------
// K4: reorder edges by dst; record = {xr element offset, norm bits}
// ---------------------------------------------------------------------------
__global__ __launch_bounds__(256) void k_reorder(const int* __restrict__ src,
                                                 const int* __restrict__ dst,
                                                 const int* __restrict__ etype,
                                                 const float* __restrict__ norm) {
    int e = blockIdx.x * blockDim.x + threadIdx.x;
    if (e >= Ee) return;
    int d   = __ldg(dst + e);
    int pos = atomicAdd(&cursor_dev[d], 1);
    uint32_t ofs = (uint32_t)((__ldg(etype + e) * Nn + __ldg(src + e)) * Dd);
    sorted_dev[pos] = make_uint2(ofs, __float_as_uint(__ldg(norm + e)));
}

// ---------------------------------------------------------------------------
// K5: per-relation GEMM on tensor cores (mma.sync m16n8k8 tf32).
// CTA: 128 M x 64 N, K=64. 4 warps, warp tile 32M x 64N.
// r < R -> fp16 message buffer xr_h; r == R -> self-loop fp32 into d_out.
// ---------------------------------------------------------------------------
#define SLD 68
#define GEMM_SMEM ((128 * SLD + 64 * SLD) * 4)   // 52224 bytes

__global__ __launch_bounds__(128) void k_gemm(const float* __restrict__ feat,
                                              float* __restrict__ d_out) {
    extern __shared__ uint32_t sh[];
    uint32_t* As = sh;                 // [128][SLD]
    uint32_t* Bs = sh + 128 * SLD;     // [64][SLD], stored [n][k]

    const int r   = blockIdx.y;
    const int nb  = blockIdx.x * 128;
    const int tid = threadIdx.x;

    {
        const uint32_t* Wsrc = (const uint32_t*)W_dev + r * Dd * Dd;  // [k][n]
#pragma unroll
        for (int it = 0; it < 32; it++) {
            int idx = tid + it * 128;
            int k = idx >> 6, n = idx & 63;
            Bs[n * SLD + k] = Wsrc[idx];
        }
    }
#pragma unroll
    for (int it = 0; it < 16; it++) {
        int lin = tid + it * 128;
        int m   = lin >> 4;
        int k4  = (lin & 15) << 2;
        int node = nb + m;
        float4 v = make_float4(0.f, 0.f, 0.f, 0.f);
        if (node < Nn) v = *(const float4*)(feat + (size_t)node * Dd + k4);
        uint32_t* p = As + m * SLD + k4;
        p[0] = f32_to_tf32(v.x); p[1] = f32_to_tf32(v.y);
        p[2] = f32_to_tf32(v.z); p[3] = f32_to_tf32(v.w);
    }
    __syncthreads();

    const int lane = tid & 31;
    const int warp = tid >> 5;
    const int g    = lane >> 2;
    const int tig  = lane & 3;
    const int mb   = warp * 32;

    float acc[2][8][4];
#pragma unroll
    for (int mf = 0; mf < 2; mf++)
#pragma unroll
        for (int nf = 0; nf < 8; nf++)
#pragma unroll
            for (int j = 0; j < 4; j++) acc[mf][nf][j] = 0.f;

#pragma unroll
    for (int k0 = 0; k0 < 64; k0 += 8) {
        uint32_t a[2][4];
#pragma unroll
        for (int mf = 0; mf < 2; mf++) {
            int row = mb + mf * 16 + g;
            a[mf][0] = As[row * SLD + k0 + tig];
            a[mf][1] = As[(row + 8) * SLD + k0 + tig];
            a[mf][2] = As[row * SLD + k0 + tig + 4];
            a[mf][3] = As[(row + 8) * SLD + k0 + tig + 4];
        }
#pragma unroll
        for (int nf = 0; nf < 8; nf++) {
            uint32_t b0 = Bs[(nf * 8 + g) * SLD + k0 + tig];
            uint32_t b1 = Bs[(nf * 8 + g) * SLD + k0 + tig + 4];
#pragma unroll
            for (int mf = 0; mf < 2; mf++) {
                asm volatile(
                    "mma.sync.aligned.m16n8k8.row.col.f32.tf32.tf32.f32 "
                    "{%0,%1,%2,%3}, {%4,%5,%6,%7}, {%8,%9}, {%0,%1,%2,%3};"
                    : "+f"(acc[mf][nf][0]), "+f"(acc[mf][nf][1]),
                      "+f"(acc[mf][nf][2]), "+f"(acc[mf][nf][3])
                    : "r"(a[mf][0]), "r"(a[mf][1]), "r"(a[mf][2]), "r"(a[mf][3]),
                      "r"(b0), "r"(b1));
            }
        }
    }

    if (r < Rr) {
        __half* outh = xr_h + (size_t)r * Nn * Dd;
#pragma unroll
        for (int mf = 0; mf < 2; mf++) {
#pragma unroll
            for (int h = 0; h < 2; h++) {
                int row = nb + mb + mf * 16 + g + h * 8;
                if (row < Nn) {
                    __half* rp = outh + (size_t)row * Dd + 2 * tig;
#pragma unroll
                    for (int nf = 0; nf < 8; nf++)
                        *(__half2*)(rp + nf * 8) =
                            __floats2half2_rn(acc[mf][nf][2 * h], acc[mf][nf][2 * h + 1]);
                }
            }
        }
    } else {
#pragma unroll
        for (int mf = 0; mf < 2; mf++) {
#pragma unroll
            for (int h = 0; h < 2; h++) {
                int row = nb + mb + mf * 16 + g + h * 8;
                if (row < Nn) {
                    float* rp = d_out + (size_t)row * Dd + 2 * tig;
#pragma unroll
                    for (int nf = 0; nf < 8; nf++)
                        *(float2*)(rp + nf * 8) =
                            make_float2(acc[mf][nf][2 * h], acc[mf][nf][2 * h + 1]);
                }
            }
        }
    }
}

// ---------------------------------------------------------------------------
// K6: atomic-free segmented aggregation + self-loop + ReLU (fused epilogue).
// 16 threads per dst node (4 cols each) walk the node's sorted edge segment.
// ---------------------------------------------------------------------------
__device__ __forceinline__ void accum_edge(float4& acc, uint2 rec, int c4) {
    uint2 raw = *(const uint2*)(xr_h + rec.x + c4);
    float2 fa = __half22float2(*(__half2*)&raw.x);
    float2 fb = __half22float2(*(__half2*)&raw.y);
    float  nm = __uint_as_float(rec.y);
    acc.x = fmaf(nm, fa.x, acc.x); acc.y = fmaf(nm, fa.y, acc.y);
    acc.z = fmaf(nm, fb.x, acc.z); acc.w = fmaf(nm, fb.y, acc.w);
}

__global__ __launch_bounds__(256) void k_agg(float* __restrict__ out) {
    const int tid  = threadIdx.x;
    const int node = blockIdx.x * 16 + (tid >> 4);
    const int c4   = (tid & 15) << 2;
    if (node >= Nn) return;

    int j   = offsets_dev[node];
    int end = offsets_dev[node + 1];

    float4 acc = make_float4(0.f, 0.f, 0.f, 0.f);
    for (; j + 3 < end; j += 4) {
        uint2 r0 = sorted_dev[j];
        uint2 r1 = sorted_dev[j + 1];
        uint2 r2 = sorted_dev[j + 2];
        uint2 r3 = sorted_dev[j + 3];
        accum_edge(acc, r0, c4);
        accum_edge(acc, r1, c4);
        accum_edge(acc, r2, c4);
        accum_edge(acc, r3, c4);
    }
    for (; j < end; j++) accum_edge(acc, sorted_dev[j], c4);

    float* rp = out + (size_t)node * Dd + c4;
    float4 self = *(const float4*)rp;   // self-loop GEMM result (pre-ReLU)
    float4 h;
    h.x = fmaxf(self.x + acc.x, 0.f);
    h.y = fmaxf(self.y + acc.y, 0.f);
    h.z = fmaxf(self.z + acc.z, 0.f);
    h.w = fmaxf(self.w + acc.w, 0.f);
    *(float4*)rp = h;
}

// ---------------------------------------------------------------------------
// Inputs (metadata order): feat, src, dst, etype, norm, weight, w_comp,
//                          self_loop_weight.  Output: float [N, 64].
// ---------------------------------------------------------------------------
extern "C" void kernel_launch(void* const* d_in, const int* in_sizes, int n_in,
                              void* d_out, int out_size) {
    const float* feat   = (const float*)d_in[0];
    const int*   src    = (const int*)d_in[1];
    const int*   dst    = (const int*)d_in[2];
    const int*   etype  = (const int*)d_in[3];
    const float* norm   = (const float*)d_in[4];
    const float* weight = (const float*)d_in[5];
    const float* w_comp = (const float*)d_in[6];
    const float* selfw  = (const float*)d_in[7];
    float* out = (float*)d_out;

    cudaFuncSetAttribute(k_gemm, cudaFuncAttributeMaxDynamicSharedMemorySize,
                         GEMM_SMEM);

    // Sort machinery
    k_zero<<<(Nn + 255) / 256, 256>>>();
    k_basis<<<176, 256>>>(weight, w_comp, selfw);
    k_hist<<<(Ee + 255) / 256, 256>>>(dst);
    k_scan_block<<<NB, 256>>>();
    k_scan_top<<<1, 256>>>();
    k_scan_down<<<NB, 256>>>();
    k_reorder<<<(Ee + 255) / 256, 256>>>(src, dst, etype, norm);

    // 11 relation GEMMs (slot R -> d_out pre-ReLU, fully overwrites out)
    dim3 g2((Nn + 127) / 128, Rr + 1);
    k_gemm<<<g2, 128, GEMM_SMEM>>>(feat, out);

    // Atomic-free aggregation + self-loop + ReLU
    k_agg<<<(Nn + 15) / 16, 256>>>(out);
}